// round 9
// baseline (speedup 1.0000x reference)
#include <cuda_runtime.h>
#include <cuda_bf16.h>
#include <cstdint>

#define NN 50000
#define EE 800000
#define LN_EPS 1e-5f
#define ST 36

// ===================== static scratch =====================
__device__ int   g_deg[NN];
__device__ int   g_rowptr[NN + 1];
__device__ int   g_cursor[NN];
__device__ int   g_csrsrc[EE];
__device__ float g_invdeg[NN];
__device__ float g_agg0[(size_t)NN * 64];           // agg(x), fp32
__device__ float g_hf0[(size_t)NN * 256];           // merged h0 fp32 (mu | v)
__device__ float g_hf1[(size_t)NN * 256];           // merged h1 fp32
__device__ float g_agg[(size_t)NN * 256];           // merged agg(h) fp32
__device__ __nv_bfloat16 g_hbf[(size_t)NN * 256];   // merged bf16 h for gathering

__device__ __forceinline__ float to_tf32(float x) {
    uint32_t u;
    asm("cvt.rna.tf32.f32 %0, %1;" : "=r"(u) : "f"(x));
    return __uint_as_float(u);
}

__device__ __forceinline__ float2 bf2f(uint32_t u) {
    return __bfloat1622float2(*reinterpret_cast<const __nv_bfloat162*>(&u));
}

__device__ __forceinline__ void mma_tf32(float& d0, float& d1, float& d2, float& d3,
                                         uint32_t a0, uint32_t a1, uint32_t a2, uint32_t a3,
                                         uint32_t b0, uint32_t b1) {
    asm volatile(
        "mma.sync.aligned.m16n8k8.row.col.f32.tf32.tf32.f32 "
        "{%0,%1,%2,%3}, {%4,%5,%6,%7}, {%8,%9}, {%0,%1,%2,%3};"
        : "+f"(d0), "+f"(d1), "+f"(d2), "+f"(d3)
        : "r"(a0), "r"(a1), "r"(a2), "r"(a3), "r"(b0), "r"(b1));
}

// ===================== CSR build =====================
__global__ void k_count(const int* __restrict__ dst, int* __restrict__ deg) {
    int e = blockIdx.x * blockDim.x + threadIdx.x;
    if (e < EE) atomicAdd(&deg[dst[e]], 1);
}

__global__ void k_scan(const int* __restrict__ deg, int* __restrict__ rowptr,
                       int* __restrict__ cursor, float* __restrict__ invdeg) {
    __shared__ int sums[1024];
    const int t = threadIdx.x;
    const int CH = (NN + 1023) / 1024;
    int s = 0;
    #pragma unroll 4
    for (int i = 0; i < CH; ++i) {
        int idx = t * CH + i;
        if (idx < NN) s += deg[idx];
    }
    sums[t] = s;
    __syncthreads();
    for (int off = 1; off < 1024; off <<= 1) {
        int v = 0;
        if (t >= off) v = sums[t - off];
        __syncthreads();
        if (t >= off) sums[t] += v;
        __syncthreads();
    }
    int run = (t == 0) ? 0 : sums[t - 1];
    for (int i = 0; i < CH; ++i) {
        int idx = t * CH + i;
        if (idx < NN) {
            int d = deg[idx];
            rowptr[idx] = run;
            cursor[idx] = run;
            invdeg[idx] = 1.0f / (float)(d > 0 ? d : 1);
            run += d;
        }
    }
    if (t == 1023) rowptr[NN] = run;
}

__global__ void k_scatter(const int* __restrict__ src, const int* __restrict__ dst,
                          int* __restrict__ cursor, int* __restrict__ csrsrc) {
    int e = blockIdx.x * blockDim.x + threadIdx.x;
    if (e < EE) {
        int pos = atomicAdd(&cursor[dst[e]], 1);
        csrsrc[pos] = src[e];
    }
}

// ===================== gathers =====================
// input features (fp32, 64-wide)
__global__ void k_gather64(const float* __restrict__ h, float* __restrict__ out,
                           const int* __restrict__ rowptr, const int* __restrict__ csrsrc,
                           const float* __restrict__ invdeg) {
    int gw   = (blockIdx.x * blockDim.x + threadIdx.x) >> 5;
    int lane = threadIdx.x & 31;
    if (gw >= NN) return;
    int s = rowptr[gw], e = rowptr[gw + 1];
    float2 a0 = make_float2(0, 0), a1 = make_float2(0, 0);
    int j = s;
    for (; j + 1 < e; j += 2) {
        int s0 = csrsrc[j], s1 = csrsrc[j + 1];
        float2 v0 = *(const float2*)(h + (size_t)s0 * 64 + lane * 2);
        float2 v1 = *(const float2*)(h + (size_t)s1 * 64 + lane * 2);
        a0.x += v0.x; a0.y += v0.y;
        a1.x += v1.x; a1.y += v1.y;
    }
    if (j < e) {
        int s0 = csrsrc[j];
        float2 v0 = *(const float2*)(h + (size_t)s0 * 64 + lane * 2);
        a0.x += v0.x; a0.y += v0.y;
    }
    float iv = invdeg[gw];
    float2 r;
    r.x = (a0.x + a1.x) * iv; r.y = (a0.y + a1.y) * iv;
    *(float2*)(out + (size_t)gw * 64 + lane * 2) = r;
}

// merged dual-tower bf16 gather: rows are 256 bf16 (512B); lane covers 8 cols
// via ONE LDG.128 per edge. Accumulates fp32, writes merged fp32 agg [N,256].
__global__ void k_gather256bf(const __nv_bfloat16* __restrict__ hb, float* __restrict__ out,
                              const int* __restrict__ rowptr, const int* __restrict__ csrsrc,
                              const float* __restrict__ invdeg) {
    int gw   = (blockIdx.x * blockDim.x + threadIdx.x) >> 5;
    int lane = threadIdx.x & 31;
    if (gw >= NN) return;
    int s = rowptr[gw], e = rowptr[gw + 1];
    float4 pA = make_float4(0, 0, 0, 0), pB = make_float4(0, 0, 0, 0);
    float4 qA = make_float4(0, 0, 0, 0), qB = make_float4(0, 0, 0, 0);
    const size_t loff = (size_t)lane * 8;
    int j = s;
    for (; j + 1 < e; j += 2) {
        const __nv_bfloat16* r0 = hb + (size_t)csrsrc[j] * 256 + loff;
        const __nv_bfloat16* r1 = hb + (size_t)csrsrc[j + 1] * 256 + loff;
        uint4 u0 = *(const uint4*)r0;
        uint4 u1 = *(const uint4*)r1;
        float2 f;
        f = bf2f(u0.x); pA.x += f.x; pA.y += f.y;
        f = bf2f(u0.y); pA.z += f.x; pA.w += f.y;
        f = bf2f(u0.z); pB.x += f.x; pB.y += f.y;
        f = bf2f(u0.w); pB.z += f.x; pB.w += f.y;
        f = bf2f(u1.x); qA.x += f.x; qA.y += f.y;
        f = bf2f(u1.y); qA.z += f.x; qA.w += f.y;
        f = bf2f(u1.z); qB.x += f.x; qB.y += f.y;
        f = bf2f(u1.w); qB.z += f.x; qB.w += f.y;
    }
    if (j < e) {
        const __nv_bfloat16* r0 = hb + (size_t)csrsrc[j] * 256 + loff;
        uint4 u0 = *(const uint4*)r0;
        float2 f;
        f = bf2f(u0.x); pA.x += f.x; pA.y += f.y;
        f = bf2f(u0.y); pA.z += f.x; pA.w += f.y;
        f = bf2f(u0.z); pB.x += f.x; pB.y += f.y;
        f = bf2f(u0.w); pB.z += f.x; pB.w += f.y;
    }
    float iv = invdeg[gw];
    float4 r;
    r.x = (pA.x + qA.x) * iv; r.y = (pA.y + qA.y) * iv;
    r.z = (pA.z + qA.z) * iv; r.w = (pA.w + qA.w) * iv;
    *(float4*)(out + (size_t)gw * 256 + lane * 8) = r;
    r.x = (pB.x + qB.x) * iv; r.y = (pB.y + qB.y) * iv;
    r.z = (pB.z + qB.z) * iv; r.w = (pB.w + qB.w) * iv;
    *(float4*)(out + (size_t)gw * 256 + lane * 8 + 4) = r;
}

// ===================== tf32 mma dense (round-3 tiling, compile-time strides) =====
// out = [Agg|Hin]@[Wl|Wr]^T + bl. 8 warps 4x2; warp tile 32x64.
// LDA/LDH/LDO are compile-time leading dimensions (merged buffers use 256).
template <int DI, int DO, int LDA, int LDH, int LDO>
__global__ __launch_bounds__(256) void k_mma(
    const float* __restrict__ Agg, const float* __restrict__ Hin,
    const float* __restrict__ Wl, const float* __restrict__ Wr,
    const float* __restrict__ bl, float* __restrict__ out) {
    constexpr int WN = DO / 2;
    constexpr int NI = WN / 8;

    __shared__ float As[128 * ST];
    __shared__ float Ws[DO * ST];

    const int tid    = threadIdx.x;
    const int wid    = tid >> 5;
    const int lane   = tid & 31;
    const int g      = lane >> 2;
    const int tig    = lane & 3;
    const int warp_m = wid >> 1;
    const int warp_n = wid & 1;
    const int bm     = blockIdx.x * 128;

    float acc[2][NI][4];
    #pragma unroll
    for (int mi = 0; mi < 2; ++mi)
        #pragma unroll
        for (int ni = 0; ni < NI; ++ni)
            #pragma unroll
            for (int q = 0; q < 4; ++q) acc[mi][ni][q] = 0.f;

    #pragma unroll
    for (int ph = 0; ph < 2; ++ph) {
        const float* __restrict__ Asrc = ph ? Hin : Agg;
        const float* __restrict__ Wsrc = ph ? Wr : Wl;
        const int lda = ph ? LDH : LDA;   // compile-time after unroll
        #pragma unroll
        for (int c = 0; c < DI / 32; ++c) {
            const int kl = c * 32;
            #pragma unroll
            for (int i = 0; i < 4; ++i) {
                int flat = tid + i * 256;
                int row = flat >> 3, q = flat & 7;
                int m = bm + row;
                float4 v = make_float4(0.f, 0.f, 0.f, 0.f);
                if (m < NN) v = *(const float4*)(Asrc + (size_t)m * lda + kl + q * 4);
                v.x = to_tf32(v.x); v.y = to_tf32(v.y); v.z = to_tf32(v.z); v.w = to_tf32(v.w);
                *(float4*)(As + row * ST + q * 4) = v;
            }
            #pragma unroll
            for (int i = 0; i < DO / 32; ++i) {
                int flat = tid + i * 256;
                int row = flat >> 3, q = flat & 7;
                float4 v = *(const float4*)(Wsrc + (size_t)row * DI + kl + q * 4);
                v.x = to_tf32(v.x); v.y = to_tf32(v.y); v.z = to_tf32(v.z); v.w = to_tf32(v.w);
                *(float4*)(Ws + row * ST + q * 4) = v;
            }
            __syncthreads();

            #pragma unroll
            for (int kk = 0; kk < 4; ++kk) {
                const int kb = kk * 8;
                uint32_t a[2][4];
                #pragma unroll
                for (int mi = 0; mi < 2; ++mi) {
                    int rb = warp_m * 32 + mi * 16;
                    a[mi][0] = __float_as_uint(As[(rb + g) * ST + kb + tig]);
                    a[mi][1] = __float_as_uint(As[(rb + g + 8) * ST + kb + tig]);
                    a[mi][2] = __float_as_uint(As[(rb + g) * ST + kb + tig + 4]);
                    a[mi][3] = __float_as_uint(As[(rb + g + 8) * ST + kb + tig + 4]);
                }
                #pragma unroll
                for (int ni = 0; ni < NI; ++ni) {
                    int nb = warp_n * WN + ni * 8;
                    uint32_t b0 = __float_as_uint(Ws[(nb + g) * ST + kb + tig]);
                    uint32_t b1 = __float_as_uint(Ws[(nb + g) * ST + kb + tig + 4]);
                    #pragma unroll
                    for (int mi = 0; mi < 2; ++mi)
                        mma_tf32(acc[mi][ni][0], acc[mi][ni][1], acc[mi][ni][2], acc[mi][ni][3],
                                 a[mi][0], a[mi][1], a[mi][2], a[mi][3], b0, b1);
                }
            }
            __syncthreads();
        }
    }

    #pragma unroll
    for (int ni = 0; ni < NI; ++ni) {
        int col = warp_n * WN + ni * 8 + tig * 2;
        float b0 = bl[col], b1 = bl[col + 1];
        #pragma unroll
        for (int mi = 0; mi < 2; ++mi) {
            int r0 = bm + warp_m * 32 + mi * 16 + g;
            if (r0 < NN)
                *(float2*)(out + (size_t)r0 * LDO + col) =
                    make_float2(acc[mi][ni][0] + b0, acc[mi][ni][1] + b1);
            int r1 = r0 + 8;
            if (r1 < NN)
                *(float2*)(out + (size_t)r1 * LDO + col) =
                    make_float2(acc[mi][ni][2] + b0, acc[mi][ni][3] + b1);
        }
    }
}

// ===================== LayerNorm + ReLU on a 128-col slice of a merged buffer =====
// h and hbf point at the tower's column offset; row stride 256 (compile-time).
__global__ void k_lnrelu(float* __restrict__ h, const float* __restrict__ g,
                         const float* __restrict__ b, __nv_bfloat16* __restrict__ hbf) {
    int n    = (blockIdx.x * blockDim.x + threadIdx.x) >> 5;
    int lane = threadIdx.x & 31;
    if (n >= NN) return;
    float4 v = *(const float4*)(h + (size_t)n * 256 + lane * 4);
    float s = v.x + v.y + v.z + v.w;
    #pragma unroll
    for (int off = 16; off > 0; off >>= 1) s += __shfl_xor_sync(0xFFFFFFFF, s, off);
    float mean = s * (1.0f / 128.0f);
    float dx = v.x - mean, dy = v.y - mean, dz = v.z - mean, dw = v.w - mean;
    float sq = dx * dx + dy * dy + dz * dz + dw * dw;
    #pragma unroll
    for (int off = 16; off > 0; off >>= 1) sq += __shfl_xor_sync(0xFFFFFFFF, sq, off);
    float rs = rsqrtf(sq * (1.0f / 128.0f) + LN_EPS);
    float4 gg = *(const float4*)(g + lane * 4);
    float4 bb = *(const float4*)(b + lane * 4);
    float4 r;
    r.x = fmaxf(dx * rs * gg.x + bb.x, 0.f);
    r.y = fmaxf(dy * rs * gg.y + bb.y, 0.f);
    r.z = fmaxf(dz * rs * gg.z + bb.z, 0.f);
    r.w = fmaxf(dw * rs * gg.w + bb.w, 0.f);
    *(float4*)(h + (size_t)n * 256 + lane * 4) = r;
    __nv_bfloat162 q0 = __floats2bfloat162_rn(r.x, r.y);
    __nv_bfloat162 q1 = __floats2bfloat162_rn(r.z, r.w);
    uint2 pk;
    pk.x = *reinterpret_cast<uint32_t*>(&q0);
    pk.y = *reinterpret_cast<uint32_t*>(&q1);
    *(uint2*)(hbf + (size_t)n * 256 + lane * 4) = pk;
}

// ===================== host =====================
extern "C" void kernel_launch(void* const* d_in, const int* in_sizes, int n_in,
                              void* d_out, int out_size) {
    const float* x   = (const float*)d_in[0];
    const int*   ei  = (const int*)d_in[1];
    const int*   src = ei;
    const int*   dst = ei + EE;

    int *pDeg, *pRow, *pCur, *pCsr;
    float *pInv, *pAgg0, *pHf0, *pHf1, *pAgg;
    __nv_bfloat16* pHbf;
    cudaGetSymbolAddress((void**)&pDeg, g_deg);
    cudaGetSymbolAddress((void**)&pRow, g_rowptr);
    cudaGetSymbolAddress((void**)&pCur, g_cursor);
    cudaGetSymbolAddress((void**)&pCsr, g_csrsrc);
    cudaGetSymbolAddress((void**)&pInv, g_invdeg);
    cudaGetSymbolAddress((void**)&pAgg0, g_agg0);
    cudaGetSymbolAddress((void**)&pHf0, g_hf0);
    cudaGetSymbolAddress((void**)&pHf1, g_hf1);
    cudaGetSymbolAddress((void**)&pAgg, g_agg);
    cudaGetSymbolAddress((void**)&pHbf, g_hbf);

    const float* W[2][13];
    for (int t = 0; t < 2; ++t)
        for (int i = 0; i < 13; ++i) W[t][i] = (const float*)d_in[2 + t * 13 + i];
    // 0 Wl0, 1 bl0, 2 Wr0, 3 g0, 4 b0, 5 Wl1, 6 bl1, 7 Wr1, 8 g1, 9 b1, 10 Wl2, 11 bl2, 12 Wr2

    const int EB = (EE + 255) / 256;
    const int GW = (NN * 32 + 255) / 256;
    const int DB = (NN + 127) / 128;

    cudaMemsetAsync(pDeg, 0, NN * sizeof(int), 0);
    k_count<<<EB, 256>>>(dst, pDeg);
    k_scan<<<1, 1024>>>(pDeg, pRow, pCur, pInv);
    k_scatter<<<EB, 256>>>(src, dst, pCur, pCsr);

    // shared input aggregation (fp32)
    k_gather64<<<GW, 256>>>(x, pAgg0, pRow, pCsr, pInv);

    // ---- layer 0: [agg0 | x] -> merged h0 ; LN+ReLU -> fp32 + bf16 merged ----
    for (int t = 0; t < 2; ++t) {
        k_mma<64, 128, 64, 64, 256><<<DB, 256>>>(
            pAgg0, x, W[t][0], W[t][2], W[t][1], pHf0 + t * 128);
        k_lnrelu<<<GW, 256>>>(pHf0 + t * 128, W[t][3], W[t][4], pHbf + t * 128);
    }

    // ---- layer 1: ONE merged gather serves both towers ----
    k_gather256bf<<<GW, 256>>>(pHbf, pAgg, pRow, pCsr, pInv);
    for (int t = 0; t < 2; ++t) {
        k_mma<128, 128, 256, 256, 256><<<DB, 256>>>(
            pAgg + t * 128, pHf0 + t * 128, W[t][5], W[t][7], W[t][6], pHf1 + t * 128);
        k_lnrelu<<<GW, 256>>>(pHf1 + t * 128, W[t][8], W[t][9], pHbf + t * 128);
    }

    // ---- layer 2: ONE merged gather, GEMMs into d_out ----
    k_gather256bf<<<GW, 256>>>(pHbf, pAgg, pRow, pCsr, pInv);
    for (int t = 0; t < 2; ++t) {
        float* outT = (float*)d_out + (size_t)t * NN * 64;
        k_mma<128, 64, 256, 256, 64><<<DB, 256>>>(
            pAgg + t * 128, pHf1 + t * 128, W[t][10], W[t][12], W[t][11], outT);
    }
}

// round 10
// speedup vs baseline: 1.0292x; 1.0292x over previous
#include <cuda_runtime.h>
#include <cuda_bf16.h>
#include <cstdint>

#define NN 50000
#define EE 800000
#define LN_EPS 1e-5f
#define ST 36

// ===================== static scratch =====================
__device__ int   g_deg[NN];
__device__ int   g_rowptr[NN + 1];
__device__ int   g_cursor[NN];
__device__ int   g_csrsrc[EE];
__device__ float g_invdeg[NN];
__device__ float g_agg0[(size_t)NN * 64];
__device__ float g_h0[2][(size_t)NN * 128];
__device__ float g_ag[2][(size_t)NN * 128];
__device__ float g_h1[2][(size_t)NN * 128];

__device__ __forceinline__ float to_tf32(float x) {
    uint32_t u;
    asm("cvt.rna.tf32.f32 %0, %1;" : "=r"(u) : "f"(x));
    return __uint_as_float(u);
}

__device__ __forceinline__ void mma_tf32(float& d0, float& d1, float& d2, float& d3,
                                         uint32_t a0, uint32_t a1, uint32_t a2, uint32_t a3,
                                         uint32_t b0, uint32_t b1) {
    asm volatile(
        "mma.sync.aligned.m16n8k8.row.col.f32.tf32.tf32.f32 "
        "{%0,%1,%2,%3}, {%4,%5,%6,%7}, {%8,%9}, {%0,%1,%2,%3};"
        : "+f"(d0), "+f"(d1), "+f"(d2), "+f"(d3)
        : "r"(a0), "r"(a1), "r"(a2), "r"(a3), "r"(b0), "r"(b1));
}

// ===================== CSR build =====================
__global__ void k_count(const int* __restrict__ dst, int* __restrict__ deg) {
    int e = blockIdx.x * blockDim.x + threadIdx.x;
    if (e < EE) atomicAdd(&deg[dst[e]], 1);
}

__global__ void k_scan(const int* __restrict__ deg, int* __restrict__ rowptr,
                       int* __restrict__ cursor, float* __restrict__ invdeg) {
    __shared__ int sums[1024];
    const int t = threadIdx.x;
    const int CH = (NN + 1023) / 1024;
    int s = 0;
    #pragma unroll 4
    for (int i = 0; i < CH; ++i) {
        int idx = t * CH + i;
        if (idx < NN) s += deg[idx];
    }
    sums[t] = s;
    __syncthreads();
    for (int off = 1; off < 1024; off <<= 1) {
        int v = 0;
        if (t >= off) v = sums[t - off];
        __syncthreads();
        if (t >= off) sums[t] += v;
        __syncthreads();
    }
    int run = (t == 0) ? 0 : sums[t - 1];
    for (int i = 0; i < CH; ++i) {
        int idx = t * CH + i;
        if (idx < NN) {
            int d = deg[idx];
            rowptr[idx] = run;
            cursor[idx] = run;
            invdeg[idx] = 1.0f / (float)(d > 0 ? d : 1);
            run += d;
        }
    }
    if (t == 1023) rowptr[NN] = run;
}

__global__ void k_scatter(const int* __restrict__ src, const int* __restrict__ dst,
                          int* __restrict__ cursor, int* __restrict__ csrsrc) {
    int e = blockIdx.x * blockDim.x + threadIdx.x;
    if (e < EE) {
        int pos = atomicAdd(&cursor[dst[e]], 1);
        csrsrc[pos] = src[e];
    }
}

// ===================== gathers (R3 form) =====================
__global__ void k_gather64(const float* __restrict__ h, float* __restrict__ out,
                           const int* __restrict__ rowptr, const int* __restrict__ csrsrc,
                           const float* __restrict__ invdeg) {
    int gw   = (blockIdx.x * blockDim.x + threadIdx.x) >> 5;
    int lane = threadIdx.x & 31;
    if (gw >= NN) return;
    int s = rowptr[gw], e = rowptr[gw + 1];
    float2 a0 = make_float2(0, 0), a1 = make_float2(0, 0);
    int j = s;
    for (; j + 1 < e; j += 2) {
        int s0 = csrsrc[j], s1 = csrsrc[j + 1];
        float2 v0 = *(const float2*)(h + (size_t)s0 * 64 + lane * 2);
        float2 v1 = *(const float2*)(h + (size_t)s1 * 64 + lane * 2);
        a0.x += v0.x; a0.y += v0.y;
        a1.x += v1.x; a1.y += v1.y;
    }
    if (j < e) {
        int s0 = csrsrc[j];
        float2 v0 = *(const float2*)(h + (size_t)s0 * 64 + lane * 2);
        a0.x += v0.x; a0.y += v0.y;
    }
    float iv = invdeg[gw];
    float2 r;
    r.x = (a0.x + a1.x) * iv; r.y = (a0.y + a1.y) * iv;
    *(float2*)(out + (size_t)gw * 64 + lane * 2) = r;
}

// dual-tower 128-wide fp32 gather: blockIdx.y selects tower
__global__ void k_gather128_2(const float* __restrict__ hA, float* __restrict__ oA,
                              const float* __restrict__ hB, float* __restrict__ oB,
                              const int* __restrict__ rowptr, const int* __restrict__ csrsrc,
                              const float* __restrict__ invdeg) {
    const float* __restrict__ h = blockIdx.y ? hB : hA;
    float* __restrict__ out     = blockIdx.y ? oB : oA;
    int gw   = (blockIdx.x * blockDim.x + threadIdx.x) >> 5;
    int lane = threadIdx.x & 31;
    if (gw >= NN) return;
    int s = rowptr[gw], e = rowptr[gw + 1];
    float4 a0 = make_float4(0, 0, 0, 0), a1 = make_float4(0, 0, 0, 0);
    int j = s;
    for (; j + 1 < e; j += 2) {
        int s0 = csrsrc[j], s1 = csrsrc[j + 1];
        float4 v0 = *(const float4*)(h + (size_t)s0 * 128 + lane * 4);
        float4 v1 = *(const float4*)(h + (size_t)s1 * 128 + lane * 4);
        a0.x += v0.x; a0.y += v0.y; a0.z += v0.z; a0.w += v0.w;
        a1.x += v1.x; a1.y += v1.y; a1.z += v1.z; a1.w += v1.w;
    }
    if (j < e) {
        int s0 = csrsrc[j];
        float4 v0 = *(const float4*)(h + (size_t)s0 * 128 + lane * 4);
        a0.x += v0.x; a0.y += v0.y; a0.z += v0.z; a0.w += v0.w;
    }
    float iv = invdeg[gw];
    float4 r;
    r.x = (a0.x + a1.x) * iv; r.y = (a0.y + a1.y) * iv;
    r.z = (a0.z + a1.z) * iv; r.w = (a0.w + a1.w) * iv;
    *(float4*)(out + (size_t)gw * 128 + lane * 4) = r;
}

// ===================== tf32 mma dense (R3 tiling, dual tower via blockIdx.y) =====
// out = [Agg|Hin]@[Wl|Wr]^T + bl. 8 warps 4x2; warp tile 32x64. Compile-time strides.
template <int DI, int DO>
__global__ __launch_bounds__(256) void k_mma(
    const float* __restrict__ AggA, const float* __restrict__ HinA,
    const float* __restrict__ WlA, const float* __restrict__ WrA,
    const float* __restrict__ blA, float* __restrict__ outA,
    const float* __restrict__ AggB, const float* __restrict__ HinB,
    const float* __restrict__ WlB, const float* __restrict__ WrB,
    const float* __restrict__ blB, float* __restrict__ outB) {
    constexpr int WN = DO / 2;
    constexpr int NI = WN / 8;

    const float* __restrict__ Agg = blockIdx.y ? AggB : AggA;
    const float* __restrict__ Hin = blockIdx.y ? HinB : HinA;
    const float* __restrict__ Wl  = blockIdx.y ? WlB : WlA;
    const float* __restrict__ Wr  = blockIdx.y ? WrB : WrA;
    const float* __restrict__ bl  = blockIdx.y ? blB : blA;
    float* __restrict__ out       = blockIdx.y ? outB : outA;

    __shared__ float As[128 * ST];
    __shared__ float Ws[DO * ST];

    const int tid    = threadIdx.x;
    const int wid    = tid >> 5;
    const int lane   = tid & 31;
    const int g      = lane >> 2;
    const int tig    = lane & 3;
    const int warp_m = wid >> 1;
    const int warp_n = wid & 1;
    const int bm     = blockIdx.x * 128;

    float acc[2][NI][4];
    #pragma unroll
    for (int mi = 0; mi < 2; ++mi)
        #pragma unroll
        for (int ni = 0; ni < NI; ++ni)
            #pragma unroll
            for (int q = 0; q < 4; ++q) acc[mi][ni][q] = 0.f;

    #pragma unroll
    for (int ph = 0; ph < 2; ++ph) {
        const float* __restrict__ Asrc = ph ? Hin : Agg;
        const float* __restrict__ Wsrc = ph ? Wr : Wl;
        #pragma unroll
        for (int c = 0; c < DI / 32; ++c) {
            const int kl = c * 32;
            #pragma unroll
            for (int i = 0; i < 4; ++i) {
                int flat = tid + i * 256;
                int row = flat >> 3, q = flat & 7;
                int m = bm + row;
                float4 v = make_float4(0.f, 0.f, 0.f, 0.f);
                if (m < NN) v = *(const float4*)(Asrc + (size_t)m * DI + kl + q * 4);
                v.x = to_tf32(v.x); v.y = to_tf32(v.y); v.z = to_tf32(v.z); v.w = to_tf32(v.w);
                *(float4*)(As + row * ST + q * 4) = v;
            }
            #pragma unroll
            for (int i = 0; i < DO / 32; ++i) {
                int flat = tid + i * 256;
                int row = flat >> 3, q = flat & 7;
                float4 v = *(const float4*)(Wsrc + (size_t)row * DI + kl + q * 4);
                v.x = to_tf32(v.x); v.y = to_tf32(v.y); v.z = to_tf32(v.z); v.w = to_tf32(v.w);
                *(float4*)(Ws + row * ST + q * 4) = v;
            }
            __syncthreads();

            #pragma unroll
            for (int kk = 0; kk < 4; ++kk) {
                const int kb = kk * 8;
                uint32_t a[2][4];
                #pragma unroll
                for (int mi = 0; mi < 2; ++mi) {
                    int rb = warp_m * 32 + mi * 16;
                    a[mi][0] = __float_as_uint(As[(rb + g) * ST + kb + tig]);
                    a[mi][1] = __float_as_uint(As[(rb + g + 8) * ST + kb + tig]);
                    a[mi][2] = __float_as_uint(As[(rb + g) * ST + kb + tig + 4]);
                    a[mi][3] = __float_as_uint(As[(rb + g + 8) * ST + kb + tig + 4]);
                }
                #pragma unroll
                for (int ni = 0; ni < NI; ++ni) {
                    int nb = warp_n * WN + ni * 8;
                    uint32_t b0 = __float_as_uint(Ws[(nb + g) * ST + kb + tig]);
                    uint32_t b1 = __float_as_uint(Ws[(nb + g) * ST + kb + tig + 4]);
                    #pragma unroll
                    for (int mi = 0; mi < 2; ++mi)
                        mma_tf32(acc[mi][ni][0], acc[mi][ni][1], acc[mi][ni][2], acc[mi][ni][3],
                                 a[mi][0], a[mi][1], a[mi][2], a[mi][3], b0, b1);
                }
            }
            __syncthreads();
        }
    }

    #pragma unroll
    for (int ni = 0; ni < NI; ++ni) {
        int col = warp_n * WN + ni * 8 + tig * 2;
        float b0 = bl[col], b1 = bl[col + 1];
        #pragma unroll
        for (int mi = 0; mi < 2; ++mi) {
            int r0 = bm + warp_m * 32 + mi * 16 + g;
            if (r0 < NN)
                *(float2*)(out + (size_t)r0 * DO + col) =
                    make_float2(acc[mi][ni][0] + b0, acc[mi][ni][1] + b1);
            int r1 = r0 + 8;
            if (r1 < NN)
                *(float2*)(out + (size_t)r1 * DO + col) =
                    make_float2(acc[mi][ni][2] + b0, acc[mi][ni][3] + b1);
        }
    }
}

// ===================== LayerNorm + ReLU, dual tower via blockIdx.y =====
__global__ void k_lnrelu2(float* __restrict__ hA, const float* __restrict__ gA,
                          const float* __restrict__ bA,
                          float* __restrict__ hB, const float* __restrict__ gB,
                          const float* __restrict__ bB) {
    float* __restrict__ h       = blockIdx.y ? hB : hA;
    const float* __restrict__ g = blockIdx.y ? gB : gA;
    const float* __restrict__ b = blockIdx.y ? bB : bA;
    int n    = (blockIdx.x * blockDim.x + threadIdx.x) >> 5;
    int lane = threadIdx.x & 31;
    if (n >= NN) return;
    float4 v = *(const float4*)(h + (size_t)n * 128 + lane * 4);
    float s = v.x + v.y + v.z + v.w;
    #pragma unroll
    for (int off = 16; off > 0; off >>= 1) s += __shfl_xor_sync(0xFFFFFFFF, s, off);
    float mean = s * (1.0f / 128.0f);
    float dx = v.x - mean, dy = v.y - mean, dz = v.z - mean, dw = v.w - mean;
    float sq = dx * dx + dy * dy + dz * dz + dw * dw;
    #pragma unroll
    for (int off = 16; off > 0; off >>= 1) sq += __shfl_xor_sync(0xFFFFFFFF, sq, off);
    float rs = rsqrtf(sq * (1.0f / 128.0f) + LN_EPS);
    float4 gg = *(const float4*)(g + lane * 4);
    float4 bb = *(const float4*)(b + lane * 4);
    float4 r;
    r.x = fmaxf(dx * rs * gg.x + bb.x, 0.f);
    r.y = fmaxf(dy * rs * gg.y + bb.y, 0.f);
    r.z = fmaxf(dz * rs * gg.z + bb.z, 0.f);
    r.w = fmaxf(dw * rs * gg.w + bb.w, 0.f);
    *(float4*)(h + (size_t)n * 128 + lane * 4) = r;
}

// ===================== host =====================
extern "C" void kernel_launch(void* const* d_in, const int* in_sizes, int n_in,
                              void* d_out, int out_size) {
    const float* x   = (const float*)d_in[0];
    const int*   ei  = (const int*)d_in[1];
    const int*   src = ei;
    const int*   dst = ei + EE;

    int *pDeg, *pRow, *pCur, *pCsr;
    float *pInv, *pAgg0, *pH0, *pAg, *pH1;
    cudaGetSymbolAddress((void**)&pDeg, g_deg);
    cudaGetSymbolAddress((void**)&pRow, g_rowptr);
    cudaGetSymbolAddress((void**)&pCur, g_cursor);
    cudaGetSymbolAddress((void**)&pCsr, g_csrsrc);
    cudaGetSymbolAddress((void**)&pInv, g_invdeg);
    cudaGetSymbolAddress((void**)&pAgg0, g_agg0);
    cudaGetSymbolAddress((void**)&pH0, g_h0);
    cudaGetSymbolAddress((void**)&pAg, g_ag);
    cudaGetSymbolAddress((void**)&pH1, g_h1);

    float* h0[2] = {pH0, pH0 + (size_t)NN * 128};
    float* ag[2] = {pAg, pAg + (size_t)NN * 128};
    float* h1[2] = {pH1, pH1 + (size_t)NN * 128};
    float* outT[2] = {(float*)d_out, (float*)d_out + (size_t)NN * 64};

    const float* W[2][13];
    for (int t = 0; t < 2; ++t)
        for (int i = 0; i < 13; ++i) W[t][i] = (const float*)d_in[2 + t * 13 + i];
    // 0 Wl0, 1 bl0, 2 Wr0, 3 g0, 4 b0, 5 Wl1, 6 bl1, 7 Wr1, 8 g1, 9 b1, 10 Wl2, 11 bl2, 12 Wr2

    const int EB = (EE + 255) / 256;
    const int GW = (NN * 32 + 255) / 256;
    const int DB = (NN + 127) / 128;

    cudaMemsetAsync(pDeg, 0, NN * sizeof(int), 0);
    k_count<<<EB, 256>>>(dst, pDeg);
    k_scan<<<1, 1024>>>(pDeg, pRow, pCur, pInv);
    k_scatter<<<EB, 256>>>(src, dst, pCur, pCsr);

    // shared input aggregation
    k_gather64<<<GW, 256>>>(x, pAgg0, pRow, pCsr, pInv);

    // ---- layer 0 (both towers in one launch) ----
    k_mma<64, 128><<<dim3(DB, 2), 256>>>(
        pAgg0, x, W[0][0], W[0][2], W[0][1], h0[0],
        pAgg0, x, W[1][0], W[1][2], W[1][1], h0[1]);
    k_lnrelu2<<<dim3(GW, 2), 256>>>(h0[0], W[0][3], W[0][4], h0[1], W[1][3], W[1][4]);

    // ---- layer 1 ----
    k_gather128_2<<<dim3(GW, 2), 256>>>(h0[0], ag[0], h0[1], ag[1], pRow, pCsr, pInv);
    k_mma<128, 128><<<dim3(DB, 2), 256>>>(
        ag[0], h0[0], W[0][5], W[0][7], W[0][6], h1[0],
        ag[1], h0[1], W[1][5], W[1][7], W[1][6], h1[1]);
    k_lnrelu2<<<dim3(GW, 2), 256>>>(h1[0], W[0][8], W[0][9], h1[1], W[1][8], W[1][9]);

    // ---- layer 2 ----
    k_gather128_2<<<dim3(GW, 2), 256>>>(h1[0], ag[0], h1[1], ag[1], pRow, pCsr, pInv);
    k_mma<128, 64><<<dim3(DB, 2), 256>>>(
        ag[0], h1[0], W[0][10], W[0][12], W[0][11], outT[0],
        ag[1], h1[1], W[1][10], W[1][12], W[1][11], outT[1]);
}